// round 1
// baseline (speedup 1.0000x reference)
#include <cuda_runtime.h>
#include <cuda_bf16.h>
#include <cstdint>

#define Bb   2
#define Nn   16384
#define Tt   2048
#define Dd   128
#define Ss   384
#define NWw  512
#define WQq  32
#define Hh   128
#define Ll   3
#define NHh  4
#define DHh  32
#define NTOKk 33
#define BN   (Bb*Nn)          // 32768
#define BKV  (Bb*NWw*Hh)      // 131072
#define PL   196608           // packed weights per layer (floats)

// ---------------- scratch (device globals; allocation-free) ----------------
__device__ float g_q   [BN*Dd];
__device__ float g_cn  [BN*Dd];
__device__ float g_h   [BN*Dd];
__device__ float g_t1  [BN*256];
__device__ float g_t2  [BN*256];
__device__ float g_t3  [BN*Dd];
__device__ float g_kv  [(size_t)BKV*256];   // also reused for FFN (BN*512 fits)
__device__ float g_aw  [Bb*Tt*Dd];
__device__ float g_sf  [Bb*Tt*Dd];
__device__ float g_wp  [Ll*PL];
__device__ int   g_tok [BN];
__device__ int   g_rm  [BKV];

__device__ __forceinline__ float sigf(float x){ return 1.f/(1.f + __expf(-x)); }

// ---------------- generic tiled SGEMM: C[M,N] = A[M,K] @ B[K,N] -------------
// M,N multiples of 128, K multiple of 32. Optional rowmap gathers A rows.
__global__ __launch_bounds__(256) void sgemm(
    const float* __restrict__ A, const float* __restrict__ Bm,
    float* __restrict__ C, int M, int N, int K, const int* __restrict__ rowmap)
{
    __shared__ float As[32*128];
    __shared__ float Bs[32*128];
    const int tid = threadIdx.x;
    const int m0 = blockIdx.y * 128;
    const int n0 = blockIdx.x * 128;
    const int tx = tid & 15, ty = tid >> 4;

    int arows[4];
#pragma unroll
    for (int i = 0; i < 4; i++) {
        int s = tid + i*256;
        int r = m0 + (s >> 3);
        arows[i] = rowmap ? rowmap[r] : r;
    }

    float acc[8][8];
#pragma unroll
    for (int i = 0; i < 8; i++)
#pragma unroll
        for (int j = 0; j < 8; j++) acc[i][j] = 0.f;

    for (int kt = 0; kt < K; kt += 32) {
#pragma unroll
        for (int i = 0; i < 4; i++) {
            int s = tid + i*256;
            int row = s >> 3;
            int k4  = (s & 7) << 2;
            float4 v = *(const float4*)(A + (size_t)arows[i]*K + kt + k4);
            As[(k4+0)*128 + row] = v.x;
            As[(k4+1)*128 + row] = v.y;
            As[(k4+2)*128 + row] = v.z;
            As[(k4+3)*128 + row] = v.w;
        }
#pragma unroll
        for (int i = 0; i < 4; i++) {
            int s = tid + i*256;
            int k  = s >> 5;
            int n4 = (s & 31) << 2;
            *(float4*)(Bs + k*128 + n4) =
                *(const float4*)(Bm + (size_t)(kt + k)*N + n0 + n4);
        }
        __syncthreads();
#pragma unroll
        for (int kk = 0; kk < 32; kk++) {
            float a[8], b[8];
            *(float4*)(a  ) = *(float4*)(As + kk*128 + ty*8);
            *(float4*)(a+4) = *(float4*)(As + kk*128 + ty*8 + 4);
            *(float4*)(b  ) = *(float4*)(Bs + kk*128 + tx*8);
            *(float4*)(b+4) = *(float4*)(Bs + kk*128 + tx*8 + 4);
#pragma unroll
            for (int i = 0; i < 8; i++)
#pragma unroll
                for (int j = 0; j < 8; j++) acc[i][j] += a[i]*b[j];
        }
        __syncthreads();
    }
#pragma unroll
    for (int i = 0; i < 8; i++) {
        size_t r = (size_t)(m0 + ty*8 + i);
        *(float4*)(C + r*N + n0 + tx*8    ) = *(float4*)(acc[i]);
        *(float4*)(C + r*N + n0 + tx*8 + 4) = *(float4*)(acc[i]+4);
    }
}

// ---------------- attention: one block per (head, window, batch) ------------
__global__ __launch_bounds__(128) void attn_kernel(
    const float* __restrict__ kv,     // (B*NW*H, 256): [K | V]
    const float* __restrict__ qg,     // (B*N, 256):   [Q | G]
    const float* __restrict__ bias,   // (B,NW,NH,WQ,H)
    const float* __restrict__ mask,   // (B,N)
    const int*   __restrict__ kidx,   // (NW*H)
    float* __restrict__ obuf)         // (B*N, 128)
{
    __shared__ float qs[32*33];
    __shared__ float ks[128*33];      // K, later reused for V
    __shared__ float sc[32*129];
    __shared__ float mv[128];
    const int t  = threadIdx.x;
    const int hd = blockIdx.x, w = blockIdx.y, b = blockIdx.z;
    const size_t kvbase = ((size_t)(b*NWw + w) * Hh) * 256 + hd*32;
    const size_t qbase  = ((size_t)(b*Nn + w*WQq)) * 256 + hd*32;

#pragma unroll
    for (int i = 0; i < 8; i++) {
        int s = t + i*128;
        int qq = s >> 5, d = s & 31;
        qs[qq*33 + d] = qg[qbase + (size_t)qq*256 + d];
    }
#pragma unroll
    for (int i = 0; i < 32; i++) {
        int s = t + i*128;
        int kk = s >> 5, d = s & 31;
        ks[kk*33 + d] = kv[kvbase + (size_t)kk*256 + d];
    }
    {
        int ki = kidx[w*Hh + t];
        mv[t] = (1.0f - mask[b*Nn + ki]) * -1e9f;
    }
    __syncthreads();

    // scores (thread t == key index)
    const float* bptr = bias + ((((size_t)b*NWw + w)*NHh + hd)*WQq)*Hh + t;
    const float mvt = mv[t];
#pragma unroll 4
    for (int qq = 0; qq < 32; qq++) {
        float a = 0.f;
#pragma unroll
        for (int d = 0; d < 32; d++) a += qs[qq*33 + d]*ks[t*33 + d];
        sc[qq*129 + t] = a*0.17677669529663689f + bptr[(size_t)qq*Hh] + mvt;
    }
    __syncthreads();

    // load V into ks while doing softmax on sc
#pragma unroll
    for (int i = 0; i < 32; i++) {
        int s = t + i*128;
        int kk = s >> 5, d = s & 31;
        ks[kk*33 + d] = kv[kvbase + (size_t)kk*256 + 128 + d];
    }
    {
        int qq = t >> 2, seg = t & 3;
        float* row = sc + qq*129 + seg*32;
        float mx = -1e30f;
#pragma unroll
        for (int j = 0; j < 32; j++) mx = fmaxf(mx, row[j]);
        mx = fmaxf(mx, __shfl_xor_sync(0xffffffffu, mx, 1));
        mx = fmaxf(mx, __shfl_xor_sync(0xffffffffu, mx, 2));
        float sum = 0.f;
#pragma unroll
        for (int j = 0; j < 32; j++) { float e = __expf(row[j]-mx); row[j] = e; sum += e; }
        sum += __shfl_xor_sync(0xffffffffu, sum, 1);
        sum += __shfl_xor_sync(0xffffffffu, sum, 2);
        float inv = 1.f/sum;
#pragma unroll
        for (int j = 0; j < 32; j++) row[j] *= inv;
    }
    __syncthreads();

    // O = attn @ V, gate with sigmoid(G), write
    {
        int qq = t >> 2, ds = (t & 3) * 8;
        float acc[8];
#pragma unroll
        for (int j = 0; j < 8; j++) acc[j] = 0.f;
#pragma unroll 8
        for (int k = 0; k < 128; k++) {
            float s = sc[qq*129 + k];
#pragma unroll
            for (int j = 0; j < 8; j++) acc[j] += s*ks[k*33 + ds + j];
        }
        size_t nrow = (size_t)(b*Nn + w*WQq + qq);
#pragma unroll
        for (int j = 0; j < 8; j++) {
            float g = qg[nrow*256 + 128 + hd*32 + ds + j];
            obuf[nrow*128 + hd*32 + ds + j] = acc[j] * sigf(g);
        }
    }
}

// ---------------- elementwise / small kernels ----------------
__global__ void ln_rows(const float* __restrict__ x, float* __restrict__ y) {
    int warp = threadIdx.x >> 5, lane = threadIdx.x & 31;
    size_t row = (size_t)blockIdx.x*8 + warp;
    float4 v = *(const float4*)(x + row*128 + lane*4);
    float s  = v.x+v.y+v.z+v.w;
    float ss = v.x*v.x+v.y*v.y+v.z*v.z+v.w*v.w;
#pragma unroll
    for (int o = 16; o; o >>= 1) { s += __shfl_xor_sync(~0u, s, o); ss += __shfl_xor_sync(~0u, ss, o); }
    float m = s*(1.f/128.f);
    float rstd = rsqrtf(ss*(1.f/128.f) - m*m + 1e-5f);
    float4 r;
    r.x = (v.x-m)*rstd; r.y = (v.y-m)*rstd; r.z = (v.z-m)*rstd; r.w = (v.w-m)*rstd;
    *(float4*)(y + row*128 + lane*4) = r;
}

// h = ln(q) * sigmoid(X[:, :128]) + X[:, 128:]
__global__ void ew_hcur(const float* __restrict__ q, const float* __restrict__ X,
                        float* __restrict__ h) {
    int warp = threadIdx.x >> 5, lane = threadIdx.x & 31;
    size_t row = (size_t)blockIdx.x*8 + warp;
    float4 v = *(const float4*)(q + row*128 + lane*4);
    float s  = v.x+v.y+v.z+v.w;
    float ss = v.x*v.x+v.y*v.y+v.z*v.z+v.w*v.w;
#pragma unroll
    for (int o = 16; o; o >>= 1) { s += __shfl_xor_sync(~0u, s, o); ss += __shfl_xor_sync(~0u, ss, o); }
    float m = s*(1.f/128.f);
    float rstd = rsqrtf(ss*(1.f/128.f) - m*m + 1e-5f);
    float4 g = *(const float4*)(X + row*256 + lane*4);
    float4 bb = *(const float4*)(X + row*256 + 128 + lane*4);
    float4 r;
    r.x = (v.x-m)*rstd*sigf(g.x) + bb.x;
    r.y = (v.y-m)*rstd*sigf(g.y) + bb.y;
    r.z = (v.z-m)*rstd*sigf(g.z) + bb.z;
    r.w = (v.w-m)*rstd*sigf(g.w) + bb.w;
    *(float4*)(h + row*128 + lane*4) = r;
}

// q += sigmoid(gate) * x   (elementwise over BN*128)
__global__ void ew_resid(float* __restrict__ q, const float* __restrict__ gate,
                         const float* __restrict__ x) {
    size_t i4 = (size_t)blockIdx.x*blockDim.x + threadIdx.x;   // BN*32 total
    float4 qq = *(float4*)(q + i4*4);
    float4 g  = *(const float4*)(gate + i4*4);
    float4 xx = *(const float4*)(x + i4*4);
    qq.x += sigf(g.x)*xx.x; qq.y += sigf(g.y)*xx.y;
    qq.z += sigf(g.z)*xx.z; qq.w += sigf(g.w)*xx.w;
    *(float4*)(q + i4*4) = qq;
}

// out[row,256] = silu(T[row, :256]) * T[row, 256:512]
__global__ void ew_glu(const float* __restrict__ T, float* __restrict__ out) {
    size_t i4 = (size_t)blockIdx.x*blockDim.x + threadIdx.x;   // BN*64 total
    size_t row = i4 >> 6;
    int c4 = (int)(i4 & 63) << 2;
    float4 a = *(const float4*)(T + row*512 + c4);
    float4 bb = *(const float4*)(T + row*512 + 256 + c4);
    float4 r;
    r.x = a.x*sigf(a.x)*bb.x; r.y = a.y*sigf(a.y)*bb.y;
    r.z = a.z*sigf(a.z)*bb.z; r.w = a.w*sigf(a.w)*bb.w;
    *(float4*)(out + row*256 + c4) = r;
}

__global__ void pack2(const float* __restrict__ s1, const float* __restrict__ s2,
                      float* __restrict__ dst, int K, int N1, int N2) {
    int tot = K*(N1+N2);
    for (int i = blockIdx.x*blockDim.x + threadIdx.x; i < tot; i += gridDim.x*blockDim.x) {
        int n = i % (N1+N2), k = i / (N1+N2);
        dst[i] = (n < N1) ? s1[k*N1 + n] : s2[k*N2 + n - N1];
    }
}

__global__ void rowmap_kernel(const int* __restrict__ kidx, int* __restrict__ rm) {
    int i = blockIdx.x*256 + threadIdx.x;         // BKV
    int b = i / (NWw*Hh);
    int r = i % (NWw*Hh);
    rm[i] = b*Nn + kidx[r];
}

__global__ void argmax_tok(const float* __restrict__ a2t, int* __restrict__ tok) {
    int warp = threadIdx.x >> 5, lane = threadIdx.x & 31;
    size_t row = (size_t)blockIdx.x*8 + warp;
    const float* p = a2t + row*Tt;
    float bv = -1e30f; int bi = 0;
    for (int j = lane; j < Tt; j += 32) { float v = p[j]; if (v > bv) { bv = v; bi = j; } }
#pragma unroll
    for (int o = 16; o; o >>= 1) {
        float ov = __shfl_xor_sync(~0u, bv, o);
        int   oi = __shfl_xor_sync(~0u, bi, o);
        if (ov > bv || (ov == bv && oi < bi)) { bv = ov; bi = oi; }
    }
    if (lane == 0) tok[row] = bi;
}

__global__ void addaw_kernel(const float* __restrict__ qin, const float* __restrict__ aw,
                             const int* __restrict__ tok, float* __restrict__ q) {
    size_t i4 = (size_t)blockIdx.x*256 + threadIdx.x;   // BN*32
    int row = (int)(i4 >> 5);
    int d4  = (int)(i4 & 31) << 2;
    int b = row >> 14;
    int t = tok[row];
    float4 v = *(const float4*)(qin + ((size_t)row << 7) + d4);
    float4 w = *(const float4*)(aw + (((size_t)b*Tt + t) << 7) + d4);
    v.x += w.x; v.y += w.y; v.z += w.z; v.w += w.w;
    *(float4*)(q + ((size_t)row << 7) + d4) = v;
}

__global__ void sfeat_kernel(const float* __restrict__ q, const float* __restrict__ mask,
                             const int* __restrict__ tok, float* __restrict__ sf) {
    size_t e = (size_t)blockIdx.x*256 + threadIdx.x;    // BN*128
    int row = (int)(e >> 7);
    int d = (int)(e & 127);
    int b = row >> 14;
    int t = tok[row];
    atomicAdd(&sf[(((size_t)b*Tt + t) << 7) + d], q[e]*mask[row]);
}

__global__ __launch_bounds__(128) void restype_kernel(
    const float* __restrict__ sf, const float* __restrict__ Wres,
    const float* __restrict__ bres, float* __restrict__ out) {
    __shared__ float sr[128];
    int t = threadIdx.x;
    size_t row = blockIdx.x;
    sr[t] = sf[row*128 + t];
    __syncthreads();
    if (t < NTOKk) {
        float acc = bres[t];
#pragma unroll 16
        for (int d = 0; d < 128; d++) acc += sr[d]*Wres[d*NTOKk + t];
        out[row*NTOKk + t] = acc;
    }
}

__global__ __launch_bounds__(128) void rupdate_kernel(
    const float* __restrict__ q, const float* __restrict__ g,
    const float* __restrict__ bb, const float* __restrict__ Wpos,
    float* __restrict__ out) {
    __shared__ float r1[128], r2[128];
    __shared__ float ms, rs;
    int d = threadIdx.x;
    size_t row = blockIdx.x;
    float x = q[row*128 + d];
    r1[d] = x; r2[d] = x*x;
    __syncthreads();
    for (int o = 64; o; o >>= 1) { if (d < o) { r1[d] += r1[d+o]; r2[d] += r2[d+o]; } __syncthreads(); }
    if (d == 0) {
        float m = r1[0]*(1.f/128.f);
        float v = r2[0]*(1.f/128.f) - m*m;
        ms = m; rs = rsqrtf(v + 1e-5f);
    }
    __syncthreads();
    float y = (x - ms)*rs*g[d] + bb[d];
    float p0 = y*Wpos[d*3], p1 = y*Wpos[d*3+1], p2 = y*Wpos[d*3+2];
    r1[d] = p0; r2[d] = p1;
    __syncthreads();
    for (int o = 64; o; o >>= 1) { if (d < o) { r1[d] += r1[d+o]; r2[d] += r2[d+o]; } __syncthreads(); }
    if (d == 0) { out[row*3] = r1[0]; out[row*3+1] = r2[0]; }
    __syncthreads();
    r1[d] = p2;
    __syncthreads();
    for (int o = 64; o; o >>= 1) { if (d < o) { r1[d] += r1[d+o]; } __syncthreads(); }
    if (d == 0) out[row*3+2] = r1[0];
}

// ---------------- host launcher ----------------
extern "C" void kernel_launch(void* const* d_in, const int* in_sizes, int n_in,
                              void* d_out, int out_size) {
    (void)in_sizes; (void)n_in; (void)out_size;
    const float* a    = (const float*)d_in[0];
    const float* qin  = (const float*)d_in[1];
    const float* c    = (const float*)d_in[2];
    const float* bias = (const float*)d_in[3];
    const float* a2t  = (const float*)d_in[4];
    const float* mask = (const float*)d_in[5];
    const int*   kidx = (const int*)  d_in[6];
    const float* a2q  = (const float*)d_in[7];
    const float* Wq   = (const float*)d_in[8];
    const float* Wk   = (const float*)d_in[9];
    const float* Wv   = (const float*)d_in[10];
    const float* Wg   = (const float*)d_in[11];
    const float* Wo   = (const float*)d_in[12];
    const float* Wcs  = (const float*)d_in[13];
    const float* Wcb  = (const float*)d_in[14];
    const float* Wog  = (const float*)d_in[15];
    const float* Wcs2 = (const float*)d_in[16];
    const float* Wcb2 = (const float*)d_in[17];
    const float* Wog2 = (const float*)d_in[18];
    const float* W1   = (const float*)d_in[19];
    const float* W2   = (const float*)d_in[20];
    const float* W3   = (const float*)d_in[21];
    const float* ln_g = (const float*)d_in[22];
    const float* ln_b = (const float*)d_in[23];
    const float* Wpos = (const float*)d_in[24];
    const float* Wres = (const float*)d_in[25];
    const float* bres = (const float*)d_in[26];
    float* out = (float*)d_out;

    float *pq, *pcn, *ph, *pt1, *pt2, *pt3, *pkv, *paw, *psf, *pwp;
    int *ptok, *prm;
    cudaGetSymbolAddress((void**)&pq,  g_q);
    cudaGetSymbolAddress((void**)&pcn, g_cn);
    cudaGetSymbolAddress((void**)&ph,  g_h);
    cudaGetSymbolAddress((void**)&pt1, g_t1);
    cudaGetSymbolAddress((void**)&pt2, g_t2);
    cudaGetSymbolAddress((void**)&pt3, g_t3);
    cudaGetSymbolAddress((void**)&pkv, g_kv);
    cudaGetSymbolAddress((void**)&paw, g_aw);
    cudaGetSymbolAddress((void**)&psf, g_sf);
    cudaGetSymbolAddress((void**)&pwp, g_wp);
    cudaGetSymbolAddress((void**)&ptok, g_tok);
    cudaGetSymbolAddress((void**)&prm,  g_rm);

    // prologue
    rowmap_kernel<<<BKV/256, 256>>>(kidx, prm);
    argmax_tok<<<BN/8, 256>>>(a2t, ptok);
    sgemm<<<dim3(1, (Bb*Tt)/128), 256>>>(a, a2q, paw, Bb*Tt, 128, Ss, nullptr);
    addaw_kernel<<<(BN*32)/256, 256>>>(qin, paw, ptok, pq);
    ln_rows<<<BN/8, 256>>>(c, pcn);

    // weight packing (per layer): [cs|cb], [q|g], [k|v], [cs2|cb2], [W1|W2]
    for (int l = 0; l < Ll; l++) {
        float* wl = pwp + l*PL;
        pack2<<<256, 256>>>(Wcs  + l*Dd*Dd, Wcb  + l*Dd*Dd, wl,          Dd, Dd, Dd);
        pack2<<<256, 256>>>(Wq   + l*Dd*Dd, Wg   + l*Dd*Dd, wl +  32768, Dd, Dd, Dd);
        pack2<<<256, 256>>>(Wk   + l*Dd*Dd, Wv   + l*Dd*Dd, wl +  65536, Dd, Dd, Dd);
        pack2<<<256, 256>>>(Wcs2 + l*Dd*Dd, Wcb2 + l*Dd*Dd, wl +  98304, Dd, Dd, Dd);
        pack2<<<256, 256>>>(W1 + l*Dd*256,  W2 + l*Dd*256,  wl + 131072, Dd, 256, 256);
    }

    for (int l = 0; l < Ll; l++) {
        const float* wl = pwp + l*PL;
        // hcur = ln(q)*sig(cn@Wcs) + cn@Wcb
        sgemm<<<dim3(2, BN/128), 256>>>(pcn, wl, pt1, BN, 256, Dd, nullptr);
        ew_hcur<<<BN/8, 256>>>(pq, pt1, ph);
        // Q|G projection
        sgemm<<<dim3(2, BN/128), 256>>>(ph, wl + 32768, pt2, BN, 256, Dd, nullptr);
        // gathered K|V projection
        sgemm<<<dim3(2, BKV/128), 256>>>(ph, wl + 65536, pkv, BKV, 256, Dd, prm);
        // attention (+ sigmoid(Wg) gate)
        attn_kernel<<<dim3(NHh, NWw, Bb), 128>>>(pkv, pt2, bias, mask, kidx, pt3);
        // q += sig(cn@Wog) * (o@Wo)
        sgemm<<<dim3(1, BN/128), 256>>>(pt3, Wo + l*Dd*Dd, pt1, BN, Dd, Dd, nullptr);
        sgemm<<<dim3(1, BN/128), 256>>>(pcn, Wog + l*Dd*Dd, pt2, BN, Dd, Dd, nullptr);
        ew_resid<<<(BN*32)/256, 256>>>(pq, pt2, pt1);
        // h2 = ln(q)*sig(cn@Wcs2) + cn@Wcb2
        sgemm<<<dim3(2, BN/128), 256>>>(pcn, wl + 98304, pt1, BN, 256, Dd, nullptr);
        ew_hcur<<<BN/8, 256>>>(pq, pt1, ph);
        // FFN: silu(h2@W1)*(h2@W2) @ W3, gated by sig(cn@Wog2)
        sgemm<<<dim3(4, BN/128), 256>>>(ph, wl + 131072, pkv, BN, 512, Dd, nullptr);
        ew_glu<<<(BN*64)/256, 256>>>(pkv, pt1);
        sgemm<<<dim3(1, BN/128), 256>>>(pt1, W3 + l*256*Dd, pt2, BN, Dd, 256, nullptr);
        sgemm<<<dim3(1, BN/128), 256>>>(pcn, Wog2 + l*Dd*Dd, pt3, BN, Dd, Dd, nullptr);
        ew_resid<<<(BN*32)/256, 256>>>(pq, pt3, pt2);
    }

    // epilogue: segment-sum -> res_type ; ln(q)*g+b @ Wpos -> r_update
    cudaMemsetAsync(psf, 0, (size_t)Bb*Tt*Dd*sizeof(float));
    sfeat_kernel<<<(BN*128)/256, 256>>>(pq, mask, ptok, psf);
    restype_kernel<<<Bb*Tt, 128>>>(psf, Wres, bres, out + (size_t)BN*3);
    rupdate_kernel<<<BN, 128>>>(pq, ln_g, ln_b, Wpos, out);
}